// round 1
// baseline (speedup 1.0000x reference)
#include <cuda_runtime.h>
#include <cuda_bf16.h>
#include <math.h>

#define NN 50000
#define NE 800000
#define HID 128
#define OUTC 40

// ---------------- scratch (no allocation allowed) ----------------
__device__ float g_h[(size_t)NN * HID];
__device__ float g_hnew[(size_t)NN * HID];
__device__ float g_m[(size_t)NN * HID];
__device__ float g_agg[(size_t)NN * HID];

// ---------------- C = A[N,128] @ W[128,128] (+bias) ----------------
// Block: 256 threads, 32-node tile. K chunked by 64.
__global__ __launch_bounds__(256) void gemm128_kernel(
    const float* __restrict__ A, const float* __restrict__ W,
    const float* __restrict__ bias, float* __restrict__ C)
{
    __shared__ float sA[32][64];
    __shared__ float sW[64][128];

    const int node0 = blockIdx.x * 32;
    const int tid = threadIdx.x;
    const int col = tid & 127;
    const int ns  = tid >> 7;   // 0..1  (16 nodes each)

    float acc[16];
#pragma unroll
    for (int i = 0; i < 16; i++) acc[i] = 0.f;

    for (int kc = 0; kc < 128; kc += 64) {
        // load A tile: 32x64 = 512 float4, 2 per thread
#pragma unroll
        for (int r = 0; r < 2; r++) {
            int id = tid + r * 256;          // 0..511
            int n  = id >> 4;                // 0..31
            int k4 = id & 15;                // 0..15
            int nn = node0 + n; if (nn >= NN) nn = NN - 1;
            float4 v = *(const float4*)(A + (size_t)nn * HID + kc + k4 * 4);
            *(float4*)&sA[n][k4 * 4] = v;
        }
        // load W tile: 64x128 = 2048 float4, 8 per thread
#pragma unroll
        for (int r = 0; r < 8; r++) {
            int id = tid + r * 256;          // 0..2047
            int k  = id >> 5;                // 0..63
            int c4 = id & 31;                // 0..31
            float4 v = *(const float4*)(W + (size_t)(kc + k) * HID + c4 * 4);
            *(float4*)&sW[k][c4 * 4] = v;
        }
        __syncthreads();

#pragma unroll 4
        for (int k = 0; k < 64; k += 4) {
            float w0 = sW[k + 0][col];
            float w1 = sW[k + 1][col];
            float w2 = sW[k + 2][col];
            float w3 = sW[k + 3][col];
#pragma unroll
            for (int i = 0; i < 16; i++) {
                float4 a = *(const float4*)&sA[ns * 16 + i][k];
                acc[i] += a.x * w0 + a.y * w1 + a.z * w2 + a.w * w3;
            }
        }
        __syncthreads();
    }

    float b = bias ? bias[col] : 0.f;
#pragma unroll
    for (int i = 0; i < 16; i++) {
        int node = node0 + ns * 16 + i;
        if (node < NN) C[(size_t)node * HID + col] = acc[i] + b;
    }
}

// ---------------- zero agg ----------------
__global__ void zero_kernel(float4* __restrict__ p, int n4)
{
    int i = blockIdx.x * blockDim.x + threadIdx.x;
    if (i < n4) p[i] = make_float4(0.f, 0.f, 0.f, 0.f);
}

// ---------------- scatter-add over edges (warp per edge, v4 RED) ----------------
__global__ __launch_bounds__(256) void scatter_kernel(
    const int* __restrict__ ei, const float* __restrict__ m, float* __restrict__ agg)
{
    const int e = blockIdx.x * 8 + (threadIdx.x >> 5);
    const int lane = threadIdx.x & 31;
    const int src = __ldg(ei + e);
    const int dst = __ldg(ei + NE + e);
    float4 v = *(const float4*)(m + (size_t)src * HID + lane * 4);
    float* p = agg + (size_t)dst * HID + lane * 4;
    asm volatile("red.global.add.v4.f32 [%0], {%1,%2,%3,%4};"
                 :: "l"(p), "f"(v.x), "f"(v.y), "f"(v.z), "f"(v.w) : "memory");
}

// ---------------- fused GRU: gi = agg@W_ih^T, gh = h@W_hh^T, gates, h_new ----------------
// Block: 256 threads. Node tile = 32, col group = 32 (grid.y = 4). K chunked by 32.
__device__ __forceinline__ float dot4(float4 a, float4 b)
{
    return a.x * b.x + a.y * b.y + a.z * b.z + a.w * b.w;
}
__device__ __forceinline__ float sigmoidf_(float x) { return 1.f / (1.f + expf(-x)); }

__global__ __launch_bounds__(256) void gru_kernel(
    const float* __restrict__ agg, const float* __restrict__ h,
    const float* __restrict__ W_ih, const float* __restrict__ W_hh,
    const float* __restrict__ b_ih, const float* __restrict__ b_hh,
    float* __restrict__ hnew)
{
    // 6 weight groups: [ih_r, ih_z, ih_n, hh_r, hh_z, hh_n], each 32 cols x 32 k, padded 36
    __shared__ float sW[6][32 * 36];
    __shared__ float sAgg[32][32];
    __shared__ float sH[32][32];

    const int node0   = blockIdx.x * 32;
    const int colBase = blockIdx.y * 32;
    const int tid = threadIdx.x;
    const int c  = tid & 31;      // col within group
    const int ns = tid >> 5;      // 0..7, 4 nodes each

    float air[4] = {0, 0, 0, 0}, aiz[4] = {0, 0, 0, 0}, ain[4] = {0, 0, 0, 0};
    float ahr[4] = {0, 0, 0, 0}, ahz[4] = {0, 0, 0, 0}, ahn[4] = {0, 0, 0, 0};

    for (int kc = 0; kc < 128; kc += 32) {
        // load weights: 6*32*32 floats = 1536 float4, 6 per thread
#pragma unroll
        for (int r = 0; r < 6; r++) {
            int id  = tid + r * 256;    // 0..1535
            int g   = id >> 8;          // 0..5
            int rem = id & 255;
            int cc  = rem >> 3;         // 0..31
            int k4  = rem & 7;          // 0..7
            const float* Wsrc = (g < 3) ? W_ih : W_hh;
            int grow = (g % 3) * HID + colBase + cc;
            float4 v = *(const float4*)(Wsrc + (size_t)grow * HID + kc + k4 * 4);
            *(float4*)&sW[g][cc * 36 + k4 * 4] = v;
        }
        // load A tiles: 32 nodes x 32 k each, 1 float4 per thread per tile
        {
            int n  = tid >> 3;   // 0..31
            int k4 = tid & 7;    // 0..7
            int nn = node0 + n; if (nn >= NN) nn = NN - 1;
            float4 va = *(const float4*)(agg + (size_t)nn * HID + kc + k4 * 4);
            float4 vh = *(const float4*)(h   + (size_t)nn * HID + kc + k4 * 4);
            *(float4*)&sAgg[n][k4 * 4] = va;
            *(float4*)&sH[n][k4 * 4]   = vh;
        }
        __syncthreads();

#pragma unroll 2
        for (int k = 0; k < 32; k += 4) {
            float4 wir = *(const float4*)&sW[0][c * 36 + k];
            float4 wiz = *(const float4*)&sW[1][c * 36 + k];
            float4 win = *(const float4*)&sW[2][c * 36 + k];
            float4 whr = *(const float4*)&sW[3][c * 36 + k];
            float4 whz = *(const float4*)&sW[4][c * 36 + k];
            float4 whn = *(const float4*)&sW[5][c * 36 + k];
#pragma unroll
            for (int i = 0; i < 4; i++) {
                float4 ag = *(const float4*)&sAgg[ns * 4 + i][k];
                float4 hh = *(const float4*)&sH[ns * 4 + i][k];
                air[i] += dot4(ag, wir);
                aiz[i] += dot4(ag, wiz);
                ain[i] += dot4(ag, win);
                ahr[i] += dot4(hh, whr);
                ahz[i] += dot4(hh, whz);
                ahn[i] += dot4(hh, whn);
            }
        }
        __syncthreads();
    }

    const int j = colBase + c;
    const float bir = b_ih[j], biz = b_ih[HID + j], bin = b_ih[2 * HID + j];
    const float bhr = b_hh[j], bhz = b_hh[HID + j], bhn = b_hh[2 * HID + j];
#pragma unroll
    for (int i = 0; i < 4; i++) {
        int node = node0 + ns * 4 + i;
        if (node < NN) {
            float r  = sigmoidf_(air[i] + bir + ahr[i] + bhr);
            float z  = sigmoidf_(aiz[i] + biz + ahz[i] + bhz);
            float nv = tanhf(ain[i] + bin + r * (ahn[i] + bhn));
            float hp = h[(size_t)node * HID + j];
            hnew[(size_t)node * HID + j] = (1.f - z) * nv + z * hp;
        }
    }
}

// ---------------- relu -> out proj (128->40) -> log_softmax ----------------
// Block: 128 threads = 4 warps, 1 node per warp.
__global__ __launch_bounds__(128) void out_kernel(
    const float* __restrict__ h, const float* __restrict__ W_out,
    const float* __restrict__ b_out, float* __restrict__ out)
{
    __shared__ float sW[128][48];
    __shared__ float sB[48];
    __shared__ float sH[4][128];

    const int tid = threadIdx.x;
    for (int i = tid; i < 128 * 48; i += 128) {
        int k = i / 48, cc = i % 48;
        sW[k][cc] = (cc < OUTC) ? W_out[(size_t)k * OUTC + cc] : 0.f;
    }
    if (tid < 48) sB[tid] = (tid < OUTC) ? b_out[tid] : 0.f;

    const int w = tid >> 5, lane = tid & 31;
    const int node = blockIdx.x * 4 + w;
    float4 hv = *(const float4*)(h + (size_t)node * HID + lane * 4);
    hv.x = fmaxf(hv.x, 0.f); hv.y = fmaxf(hv.y, 0.f);
    hv.z = fmaxf(hv.z, 0.f); hv.w = fmaxf(hv.w, 0.f);
    *(float4*)&sH[w][lane * 4] = hv;
    __syncthreads();

    const int c1 = 32 + (lane & 7);
    float acc0 = 0.f, acc1 = 0.f;
#pragma unroll 4
    for (int k = 0; k < 128; k++) {
        float a = sH[w][k];
        acc0 += a * sW[k][lane];
        acc1 += a * sW[k][c1];
    }
    float v0 = acc0 + sB[lane];
    float v1 = acc1 + sB[c1];
    const bool has1 = lane < 8;

    float mx = fmaxf(v0, has1 ? v1 : -INFINITY);
#pragma unroll
    for (int o = 16; o > 0; o >>= 1) mx = fmaxf(mx, __shfl_xor_sync(0xFFFFFFFFu, mx, o));
    float s = expf(v0 - mx) + (has1 ? expf(v1 - mx) : 0.f);
#pragma unroll
    for (int o = 16; o > 0; o >>= 1) s += __shfl_xor_sync(0xFFFFFFFFu, s, o);
    float lse = mx + logf(s);

    out[(size_t)node * OUTC + lane] = v0 - lse;
    if (has1) out[(size_t)node * OUTC + 32 + lane] = v1 - lse;
}

// ---------------- launch ----------------
extern "C" void kernel_launch(void* const* d_in, const int* in_sizes, int n_in,
                              void* d_out, int out_size)
{
    const float* x       = (const float*)d_in[0];
    const int*   ei      = (const int*)  d_in[1];
    const float* W_in    = (const float*)d_in[2];
    const float* b_in    = (const float*)d_in[3];
    const float* layer_W = (const float*)d_in[4];
    const float* W_ih    = (const float*)d_in[5];
    const float* W_hh    = (const float*)d_in[6];
    const float* b_ih    = (const float*)d_in[7];
    const float* b_hh    = (const float*)d_in[8];
    const float* W_out   = (const float*)d_in[9];
    const float* b_out   = (const float*)d_in[10];

    float *hbuf, *mbuf, *aggbuf, *hnewbuf;
    cudaGetSymbolAddress((void**)&hbuf,    g_h);
    cudaGetSymbolAddress((void**)&mbuf,    g_m);
    cudaGetSymbolAddress((void**)&aggbuf,  g_agg);
    cudaGetSymbolAddress((void**)&hnewbuf, g_hnew);

    const int gemmBlocks = (NN + 31) / 32;   // 1563
    const int n4 = NN * HID / 4;             // 1.6M

    gemm128_kernel<<<gemmBlocks, 256>>>(x, W_in, b_in, hbuf);

    float* hcur = hbuf;
    float* hnext = hnewbuf;
    for (int L = 0; L < 3; L++) {
        gemm128_kernel<<<gemmBlocks, 256>>>(hcur, layer_W + (size_t)L * HID * HID, nullptr, mbuf);
        zero_kernel<<<(n4 + 255) / 256, 256>>>((float4*)aggbuf, n4);
        scatter_kernel<<<NE / 8, 256>>>(ei, mbuf, aggbuf);
        gru_kernel<<<dim3(gemmBlocks, 4), 256>>>(aggbuf, hcur, W_ih, W_hh, b_ih, b_hh, hnext);
        float* t = hcur; hcur = hnext; hnext = t;
    }

    out_kernel<<<NN / 4, 128>>>(hcur, W_out, b_out, (float*)d_out);
}

// round 2
// speedup vs baseline: 1.0191x; 1.0191x over previous
#include <cuda_runtime.h>
#include <cuda_bf16.h>
#include <math.h>

#define NN 50000
#define NE 800000
#define HID 128
#define OUTC 40

// ---------------- scratch (no allocation allowed) ----------------
__device__ float g_h[(size_t)NN * HID];
__device__ float g_hnew[(size_t)NN * HID];
__device__ float g_m[(size_t)NN * HID];
__device__ float g_agg[(size_t)NN * HID];

// ---------------- packed f32x2 helpers ----------------
typedef unsigned long long ull;

__device__ __forceinline__ ull ffma2(ull a, ull b, ull c)
{
    ull d;
    asm("fma.rn.f32x2 %0, %1, %2, %3;" : "=l"(d) : "l"(a), "l"(b), "l"(c));
    return d;
}
__device__ __forceinline__ void unpack2(ull v, float& lo, float& hi)
{
    asm("mov.b64 {%0, %1}, %2;" : "=f"(lo), "=f"(hi) : "l"(v));
}

__device__ __forceinline__ float sigmoidf_(float x) { return 1.f / (1.f + expf(-x)); }

// ---------------- C = A[N,128] @ W[128,128] (+bias), FFMA2 ----------------
// Block 256 threads: 128-node x 128-col tile. Thread: 8 nodes x 4 col-pairs.
__global__ __launch_bounds__(256, 2) void gemm128_f2_kernel(
    const float* __restrict__ A, const float* __restrict__ W,
    const float* __restrict__ bias, float* __restrict__ C)
{
    __shared__ float2 sA2[16][128];   // [k][node], duplicated {a,a}
    __shared__ float  sW[16][128];    // [k][col]

    const int tid   = threadIdx.x;
    const int cg    = tid & 15;       // col-pair group
    const int row   = tid >> 4;       // 0..15, 8 nodes each
    const int node0 = blockIdx.x * 128;

    ull acc[8][4];
#pragma unroll
    for (int i = 0; i < 8; i++)
#pragma unroll
        for (int j = 0; j < 4; j++) acc[i][j] = 0ull;

    for (int kc = 0; kc < 128; kc += 16) {
        // A tile: 128 nodes x 16 k = 512 float4, 2 per thread
#pragma unroll
        for (int r = 0; r < 2; r++) {
            int id   = tid + r * 256;       // 0..511
            int node = id >> 2;             // 0..127
            int k4   = id & 3;
            int nn   = node0 + node; if (nn >= NN) nn = NN - 1;
            float4 v = *(const float4*)(A + (size_t)nn * HID + kc + k4 * 4);
            sA2[k4 * 4 + 0][node] = make_float2(v.x, v.x);
            sA2[k4 * 4 + 1][node] = make_float2(v.y, v.y);
            sA2[k4 * 4 + 2][node] = make_float2(v.z, v.z);
            sA2[k4 * 4 + 3][node] = make_float2(v.w, v.w);
        }
        // W tile: 16 k x 128 cols = 512 float4, 2 per thread
#pragma unroll
        for (int r = 0; r < 2; r++) {
            int id = tid + r * 256;         // 0..511
            int k  = id >> 5;               // 0..15
            int c4 = id & 31;
            float4 v = *(const float4*)(W + (size_t)(kc + k) * HID + c4 * 4);
            *(float4*)&sW[k][c4 * 4] = v;
        }
        __syncthreads();

#pragma unroll
        for (int k = 0; k < 16; k++) {
            ull w2[4];
#pragma unroll
            for (int j = 0; j < 4; j++)
                w2[j] = *(const ull*)&sW[k][(cg + 16 * j) * 2];
            ull aa[8];
#pragma unroll
            for (int i = 0; i < 8; i++)
                aa[i] = *(const ull*)&sA2[k][row * 8 + i];
#pragma unroll
            for (int i = 0; i < 8; i++)
#pragma unroll
                for (int j = 0; j < 4; j++)
                    acc[i][j] = ffma2(aa[i], w2[j], acc[i][j]);
        }
        __syncthreads();
    }

    float b0[4], b1[4];
#pragma unroll
    for (int j = 0; j < 4; j++) {
        int c = (cg + 16 * j) * 2;
        b0[j] = bias ? bias[c]     : 0.f;
        b1[j] = bias ? bias[c + 1] : 0.f;
    }
#pragma unroll
    for (int i = 0; i < 8; i++) {
        int node = node0 + row * 8 + i;
        if (node < NN) {
#pragma unroll
            for (int j = 0; j < 4; j++) {
                float lo, hi;
                unpack2(acc[i][j], lo, hi);
                *(float2*)&C[(size_t)node * HID + (cg + 16 * j) * 2] =
                    make_float2(lo + b0[j], hi + b1[j]);
            }
        }
    }
}

// ---------------- zero agg ----------------
__global__ void zero_kernel(float4* __restrict__ p, int n4)
{
    int i = blockIdx.x * blockDim.x + threadIdx.x;
    if (i < n4) p[i] = make_float4(0.f, 0.f, 0.f, 0.f);
}

// ---------------- scatter-add over edges (warp per edge, v4 RED) ----------------
__global__ __launch_bounds__(256) void scatter_kernel(
    const int* __restrict__ ei, const float* __restrict__ m, float* __restrict__ agg)
{
    const int e = blockIdx.x * 8 + (threadIdx.x >> 5);
    const int lane = threadIdx.x & 31;
    const int src = __ldg(ei + e);
    const int dst = __ldg(ei + NE + e);
    float4 v = *(const float4*)(m + (size_t)src * HID + lane * 4);
    float* p = agg + (size_t)dst * HID + lane * 4;
    asm volatile("red.global.add.v4.f32 [%0], {%1,%2,%3,%4};"
                 :: "l"(p), "f"(v.x), "f"(v.y), "f"(v.z), "f"(v.w) : "memory");
}

// ---------------- fused GRU with FFMA2 ----------------
// grid (ceil(NN/96), 4). Block 256: 16 col-pairs (32 cols) x 16 rowgroups x 6 nodes.
__global__ __launch_bounds__(256, 2) void gru_f2_kernel(
    const float* __restrict__ agg, const float* __restrict__ h,
    const float* __restrict__ W_ih, const float* __restrict__ W_hh,
    const float* __restrict__ b_ih, const float* __restrict__ b_hh,
    float* __restrict__ hnew)
{
    __shared__ float2 sA2[16][96];     // duplicated agg
    __shared__ float2 sH2[16][96];     // duplicated h
    __shared__ float  sW[6][16][32];   // [gate][k][col within group]

    const int tid     = threadIdx.x;
    const int cg      = tid & 15;      // col-pair (cols colBase+2cg, +1)
    const int rowg    = tid >> 4;      // 0..15, 6 nodes each
    const int node0   = blockIdx.x * 96;
    const int colBase = blockIdx.y * 32;

    ull aI[3][6], aH[3][6];
#pragma unroll
    for (int g = 0; g < 3; g++)
#pragma unroll
        for (int i = 0; i < 6; i++) { aI[g][i] = 0ull; aH[g][i] = 0ull; }

    for (int kc = 0; kc < 128; kc += 16) {
        // A tiles: 96 nodes x 16 k = 384 float4 each
#pragma unroll
        for (int r = 0; r < 2; r++) {
            int id = tid + r * 256;
            if (id < 384) {
                int node = id >> 2;
                int k4   = id & 3;
                int nn   = node0 + node; if (nn >= NN) nn = NN - 1;
                float4 va = *(const float4*)(agg + (size_t)nn * HID + kc + k4 * 4);
                float4 vh = *(const float4*)(h   + (size_t)nn * HID + kc + k4 * 4);
                sA2[k4 * 4 + 0][node] = make_float2(va.x, va.x);
                sA2[k4 * 4 + 1][node] = make_float2(va.y, va.y);
                sA2[k4 * 4 + 2][node] = make_float2(va.z, va.z);
                sA2[k4 * 4 + 3][node] = make_float2(va.w, va.w);
                sH2[k4 * 4 + 0][node] = make_float2(vh.x, vh.x);
                sH2[k4 * 4 + 1][node] = make_float2(vh.y, vh.y);
                sH2[k4 * 4 + 2][node] = make_float2(vh.z, vh.z);
                sH2[k4 * 4 + 3][node] = make_float2(vh.w, vh.w);
            }
        }
        // W tiles: 6 gates x 32 cols x 16 k = 768 float4, 3 per thread
#pragma unroll
        for (int r = 0; r < 3; r++) {
            int id  = tid + r * 256;   // 0..767
            int g   = id >> 7;         // 0..5
            int rem = id & 127;
            int col = rem >> 2;        // 0..31
            int k4  = rem & 3;
            const float* Wp = (g < 3) ? W_ih : W_hh;
            int grow = (g % 3) * HID + colBase + col;
            float4 v = *(const float4*)(Wp + (size_t)grow * HID + kc + k4 * 4);
            sW[g][k4 * 4 + 0][col] = v.x;
            sW[g][k4 * 4 + 1][col] = v.y;
            sW[g][k4 * 4 + 2][col] = v.z;
            sW[g][k4 * 4 + 3][col] = v.w;
        }
        __syncthreads();

#pragma unroll
        for (int k = 0; k < 16; k++) {
            ull w2[6];
#pragma unroll
            for (int g = 0; g < 6; g++)
                w2[g] = *(const ull*)&sW[g][k][2 * cg];
#pragma unroll
            for (int i = 0; i < 6; i++) {
                ull aa = *(const ull*)&sA2[k][rowg * 6 + i];
                ull hh = *(const ull*)&sH2[k][rowg * 6 + i];
                aI[0][i] = ffma2(aa, w2[0], aI[0][i]);
                aI[1][i] = ffma2(aa, w2[1], aI[1][i]);
                aI[2][i] = ffma2(aa, w2[2], aI[2][i]);
                aH[0][i] = ffma2(hh, w2[3], aH[0][i]);
                aH[1][i] = ffma2(hh, w2[4], aH[1][i]);
                aH[2][i] = ffma2(hh, w2[5], aH[2][i]);
            }
        }
        __syncthreads();
    }

    const int j0 = colBase + 2 * cg;
    const float bir0 = b_ih[j0],           bir1 = b_ih[j0 + 1];
    const float biz0 = b_ih[HID + j0],     biz1 = b_ih[HID + j0 + 1];
    const float bin0 = b_ih[2 * HID + j0], bin1 = b_ih[2 * HID + j0 + 1];
    const float bhr0 = b_hh[j0],           bhr1 = b_hh[j0 + 1];
    const float bhz0 = b_hh[HID + j0],     bhz1 = b_hh[HID + j0 + 1];
    const float bhn0 = b_hh[2 * HID + j0], bhn1 = b_hh[2 * HID + j0 + 1];

#pragma unroll
    for (int i = 0; i < 6; i++) {
        int node = node0 + rowg * 6 + i;
        if (node < NN) {
            float ir0, ir1, iz0, iz1, in0, in1;
            float hr0, hr1, hz0, hz1, hn0, hn1;
            unpack2(aI[0][i], ir0, ir1);
            unpack2(aI[1][i], iz0, iz1);
            unpack2(aI[2][i], in0, in1);
            unpack2(aH[0][i], hr0, hr1);
            unpack2(aH[1][i], hz0, hz1);
            unpack2(aH[2][i], hn0, hn1);

            float2 hp = *(const float2*)(h + (size_t)node * HID + j0);

            float r0 = sigmoidf_(ir0 + bir0 + hr0 + bhr0);
            float z0 = sigmoidf_(iz0 + biz0 + hz0 + bhz0);
            float n0 = tanhf(in0 + bin0 + r0 * (hn0 + bhn0));
            float r1 = sigmoidf_(ir1 + bir1 + hr1 + bhr1);
            float z1 = sigmoidf_(iz1 + biz1 + hz1 + bhz1);
            float n1 = tanhf(in1 + bin1 + r1 * (hn1 + bhn1));

            *(float2*)&hnew[(size_t)node * HID + j0] =
                make_float2((1.f - z0) * n0 + z0 * hp.x,
                            (1.f - z1) * n1 + z1 * hp.y);
        }
    }
}

// ---------------- relu -> out proj (128->40) -> log_softmax ----------------
__global__ __launch_bounds__(128) void out_kernel(
    const float* __restrict__ h, const float* __restrict__ W_out,
    const float* __restrict__ b_out, float* __restrict__ out)
{
    __shared__ float sW[128][48];
    __shared__ float sB[48];
    __shared__ float sH[4][128];

    const int tid = threadIdx.x;
    for (int i = tid; i < 128 * 48; i += 128) {
        int k = i / 48, cc = i % 48;
        sW[k][cc] = (cc < OUTC) ? W_out[(size_t)k * OUTC + cc] : 0.f;
    }
    if (tid < 48) sB[tid] = (tid < OUTC) ? b_out[tid] : 0.f;

    const int w = tid >> 5, lane = tid & 31;
    const int node = blockIdx.x * 4 + w;
    float4 hv = *(const float4*)(h + (size_t)node * HID + lane * 4);
    hv.x = fmaxf(hv.x, 0.f); hv.y = fmaxf(hv.y, 0.f);
    hv.z = fmaxf(hv.z, 0.f); hv.w = fmaxf(hv.w, 0.f);
    *(float4*)&sH[w][lane * 4] = hv;
    __syncthreads();

    const int c1 = 32 + (lane & 7);
    float acc0 = 0.f, acc1 = 0.f;
#pragma unroll 4
    for (int k = 0; k < 128; k++) {
        float a = sH[w][k];
        acc0 += a * sW[k][lane];
        acc1 += a * sW[k][c1];
    }
    float v0 = acc0 + sB[lane];
    float v1 = acc1 + sB[c1];
    const bool has1 = lane < 8;

    float mx = fmaxf(v0, has1 ? v1 : -INFINITY);
#pragma unroll
    for (int o = 16; o > 0; o >>= 1) mx = fmaxf(mx, __shfl_xor_sync(0xFFFFFFFFu, mx, o));
    float s = expf(v0 - mx) + (has1 ? expf(v1 - mx) : 0.f);
#pragma unroll
    for (int o = 16; o > 0; o >>= 1) s += __shfl_xor_sync(0xFFFFFFFFu, s, o);
    float lse = mx + logf(s);

    out[(size_t)node * OUTC + lane] = v0 - lse;
    if (has1) out[(size_t)node * OUTC + 32 + lane] = v1 - lse;
}

// ---------------- launch ----------------
extern "C" void kernel_launch(void* const* d_in, const int* in_sizes, int n_in,
                              void* d_out, int out_size)
{
    const float* x       = (const float*)d_in[0];
    const int*   ei      = (const int*)  d_in[1];
    const float* W_in    = (const float*)d_in[2];
    const float* b_in    = (const float*)d_in[3];
    const float* layer_W = (const float*)d_in[4];
    const float* W_ih    = (const float*)d_in[5];
    const float* W_hh    = (const float*)d_in[6];
    const float* b_ih    = (const float*)d_in[7];
    const float* b_hh    = (const float*)d_in[8];
    const float* W_out   = (const float*)d_in[9];
    const float* b_out   = (const float*)d_in[10];

    float *hbuf, *mbuf, *aggbuf, *hnewbuf;
    cudaGetSymbolAddress((void**)&hbuf,    g_h);
    cudaGetSymbolAddress((void**)&mbuf,    g_m);
    cudaGetSymbolAddress((void**)&aggbuf,  g_agg);
    cudaGetSymbolAddress((void**)&hnewbuf, g_hnew);

    const int gemmBlocks = (NN + 127) / 128;   // 391
    const int gruBlocksX = (NN + 95) / 96;     // 521
    const int n4 = NN * HID / 4;               // 1.6M

    gemm128_f2_kernel<<<gemmBlocks, 256>>>(x, W_in, b_in, hbuf);

    float* hcur = hbuf;
    float* hnext = hnewbuf;
    for (int L = 0; L < 3; L++) {
        gemm128_f2_kernel<<<gemmBlocks, 256>>>(hcur, layer_W + (size_t)L * HID * HID, nullptr, mbuf);
        zero_kernel<<<(n4 + 255) / 256, 256>>>((float4*)aggbuf, n4);
        scatter_kernel<<<NE / 8, 256>>>(ei, mbuf, aggbuf);
        gru_f2_kernel<<<dim3(gruBlocksX, 4), 256>>>(aggbuf, hcur, W_ih, W_hh, b_ih, b_hh, hnext);
        float* t = hcur; hcur = hnext; hnext = t;
    }

    out_kernel<<<NN / 4, 128>>>(hcur, W_out, b_out, (float*)d_out);
}

// round 5
// speedup vs baseline: 1.0387x; 1.0193x over previous
#include <cuda_runtime.h>
#include <cuda_bf16.h>
#include <math.h>

#define NN 50000
#define NE 800000
#define HID 128
#define OUTC 40

// ---------------- scratch (no allocation allowed) ----------------
__device__ float g_h[(size_t)NN * HID];
__device__ float g_hnew[(size_t)NN * HID];
__device__ float g_m[(size_t)NN * HID];
__device__ float g_agg[(size_t)NN * HID];

// ---------------- packed f32x2 helpers ----------------
typedef unsigned long long ull;

__device__ __forceinline__ ull ffma2(ull a, ull b, ull c)
{
    ull d;
    asm("fma.rn.f32x2 %0, %1, %2, %3;" : "=l"(d) : "l"(a), "l"(b), "l"(c));
    return d;
}
__device__ __forceinline__ void unpack2(ull v, float& lo, float& hi)
{
    asm("mov.b64 {%0, %1}, %2;" : "=f"(lo), "=f"(hi) : "l"(v));
}

__device__ __forceinline__ float sigmoidf_(float x) { return 1.f / (1.f + expf(-x)); }

// ---------------- C = A[N,128] @ W[128,128] (+bias), FFMA2 ----------------
// Block 256 threads: 128-node x 128-col tile. Thread: 8 nodes x 4 col-pairs.
// (identical to the Round-2 kernel that passed)
__global__ __launch_bounds__(256, 2) void gemm128_f2_kernel(
    const float* __restrict__ A, const float* __restrict__ W,
    const float* __restrict__ bias, float* __restrict__ C)
{
    __shared__ float2 sA2[16][128];   // [k][node], duplicated {a,a}
    __shared__ float  sW[16][128];    // [k][col]

    const int tid   = threadIdx.x;
    const int cg    = tid & 15;       // col-pair group
    const int row   = tid >> 4;       // 0..15, 8 nodes each
    const int node0 = blockIdx.x * 128;

    ull acc[8][4];
#pragma unroll
    for (int i = 0; i < 8; i++)
#pragma unroll
        for (int j = 0; j < 4; j++) acc[i][j] = 0ull;

    for (int kc = 0; kc < 128; kc += 16) {
        // A tile: 128 nodes x 16 k = 512 float4, 2 per thread
#pragma unroll
        for (int r = 0; r < 2; r++) {
            int id   = tid + r * 256;       // 0..511
            int node = id >> 2;             // 0..127
            int k4   = id & 3;
            int nn   = node0 + node; if (nn >= NN) nn = NN - 1;
            float4 v = *(const float4*)(A + (size_t)nn * HID + kc + k4 * 4);
            sA2[k4 * 4 + 0][node] = make_float2(v.x, v.x);
            sA2[k4 * 4 + 1][node] = make_float2(v.y, v.y);
            sA2[k4 * 4 + 2][node] = make_float2(v.z, v.z);
            sA2[k4 * 4 + 3][node] = make_float2(v.w, v.w);
        }
        // W tile: 16 k x 128 cols = 512 float4, 2 per thread
#pragma unroll
        for (int r = 0; r < 2; r++) {
            int id = tid + r * 256;         // 0..511
            int k  = id >> 5;               // 0..15
            int c4 = id & 31;
            float4 v = *(const float4*)(W + (size_t)(kc + k) * HID + c4 * 4);
            *(float4*)&sW[k][c4 * 4] = v;
        }
        __syncthreads();

#pragma unroll
        for (int k = 0; k < 16; k++) {
            ull w2[4];
#pragma unroll
            for (int j = 0; j < 4; j++)
                w2[j] = *(const ull*)&sW[k][(cg + 16 * j) * 2];
            ull aa[8];
#pragma unroll
            for (int i = 0; i < 8; i++)
                aa[i] = *(const ull*)&sA2[k][row * 8 + i];
#pragma unroll
            for (int i = 0; i < 8; i++)
#pragma unroll
                for (int j = 0; j < 4; j++)
                    acc[i][j] = ffma2(aa[i], w2[j], acc[i][j]);
        }
        __syncthreads();
    }

    float b0[4], b1[4];
#pragma unroll
    for (int j = 0; j < 4; j++) {
        int c = (cg + 16 * j) * 2;
        b0[j] = bias ? bias[c]     : 0.f;
        b1[j] = bias ? bias[c + 1] : 0.f;
    }
#pragma unroll
    for (int i = 0; i < 8; i++) {
        int node = node0 + row * 8 + i;
        if (node < NN) {
#pragma unroll
            for (int j = 0; j < 4; j++) {
                float lo, hi;
                unpack2(acc[i][j], lo, hi);
                *(float2*)&C[(size_t)node * HID + (cg + 16 * j) * 2] =
                    make_float2(lo + b0[j], hi + b1[j]);
            }
        }
    }
}

// ---------------- zero agg ----------------
__global__ void zero_kernel(float4* __restrict__ p, int n4)
{
    int i = blockIdx.x * blockDim.x + threadIdx.x;
    if (i < n4) p[i] = make_float4(0.f, 0.f, 0.f, 0.f);
}

// ---------------- scatter-add over edges (warp per edge, v4 RED) ----------------
__global__ __launch_bounds__(256) void scatter_kernel(
    const int* __restrict__ ei, const float* __restrict__ m, float* __restrict__ agg)
{
    const int e = blockIdx.x * 8 + (threadIdx.x >> 5);
    const int lane = threadIdx.x & 31;
    const int src = __ldg(ei + e);
    const int dst = __ldg(ei + NE + e);
    float4 v = *(const float4*)(m + (size_t)src * HID + lane * 4);
    float* p = agg + (size_t)dst * HID + lane * 4;
    asm volatile("red.global.add.v4.f32 [%0], {%1,%2,%3,%4};"
                 :: "l"(p), "f"(v.x), "f"(v.y), "f"(v.z), "f"(v.w) : "memory");
}

// ---------------- fused GRU with FFMA2, spill-free tile ----------------
// grid (ceil(NN/64), 4). Block 256: 16 col-pairs (32 cols) x 16 rowgroups x 4 nodes.
__global__ __launch_bounds__(256, 2) void gru_f2_kernel(
    const float* __restrict__ agg, const float* __restrict__ h,
    const float* __restrict__ W_ih, const float* __restrict__ W_hh,
    const float* __restrict__ b_ih, const float* __restrict__ b_hh,
    float* __restrict__ hnew)
{
    __shared__ float2 sA2[16][65];     // duplicated agg, pad 65
    __shared__ float2 sH2[16][65];     // duplicated h
    __shared__ float  sW[6][16][34];   // [gate][k][col], pad 34

    const int tid   = threadIdx.x;
    const int cg    = tid & 15;        // col-pair
    const int rowg  = tid >> 4;        // 0..15, 4 nodes each
    const int node0 = blockIdx.x * 64;
    const int colB  = blockIdx.y * 32;

    ull aI[3][4], aH[3][4];
#pragma unroll
    for (int g = 0; g < 3; g++)
#pragma unroll
        for (int i = 0; i < 4; i++) { aI[g][i] = 0ull; aH[g][i] = 0ull; }

    for (int kc = 0; kc < 128; kc += 16) {
        // A/H tiles: 64 nodes x 16 k = 256 float4 each, 1 per thread per array
        {
            int node = tid >> 2;           // 0..63
            int k4   = tid & 3;
            int nn   = node0 + node; if (nn >= NN) nn = NN - 1;
            float4 va = *(const float4*)(agg + (size_t)nn * HID + kc + k4 * 4);
            float4 vh = *(const float4*)(h   + (size_t)nn * HID + kc + k4 * 4);
            sA2[k4 * 4 + 0][node] = make_float2(va.x, va.x);
            sA2[k4 * 4 + 1][node] = make_float2(va.y, va.y);
            sA2[k4 * 4 + 2][node] = make_float2(va.z, va.z);
            sA2[k4 * 4 + 3][node] = make_float2(va.w, va.w);
            sH2[k4 * 4 + 0][node] = make_float2(vh.x, vh.x);
            sH2[k4 * 4 + 1][node] = make_float2(vh.y, vh.y);
            sH2[k4 * 4 + 2][node] = make_float2(vh.z, vh.z);
            sH2[k4 * 4 + 3][node] = make_float2(vh.w, vh.w);
        }
        // W tiles: 6 gates x 32 cols x 16 k = 768 float4, 3 per thread
#pragma unroll
        for (int r = 0; r < 3; r++) {
            int id  = tid + r * 256;       // 0..767
            int g   = id >> 7;             // 0..5
            int rem = id & 127;
            int col = rem >> 2;            // 0..31
            int k4  = rem & 3;
            const float* Wp = (g < 3) ? W_ih : W_hh;
            int grow = (g % 3) * HID + colB + col;
            float4 v = *(const float4*)(Wp + (size_t)grow * HID + kc + k4 * 4);
            sW[g][k4 * 4 + 0][col] = v.x;
            sW[g][k4 * 4 + 1][col] = v.y;
            sW[g][k4 * 4 + 2][col] = v.z;
            sW[g][k4 * 4 + 3][col] = v.w;
        }
        __syncthreads();

#pragma unroll
        for (int k = 0; k < 16; k++) {
            ull w0 = *(const ull*)&sW[0][k][2 * cg];
            ull w1 = *(const ull*)&sW[1][k][2 * cg];
            ull w2 = *(const ull*)&sW[2][k][2 * cg];
            ull w3 = *(const ull*)&sW[3][k][2 * cg];
            ull w4 = *(const ull*)&sW[4][k][2 * cg];
            ull w5 = *(const ull*)&sW[5][k][2 * cg];
            const ull* ap = (const ull*)&sA2[k][rowg * 4];
            const ull* hp = (const ull*)&sH2[k][rowg * 4];
#pragma unroll
            for (int i = 0; i < 4; i++) {
                ull a  = ap[i];
                ull hh = hp[i];
                aI[0][i] = ffma2(a,  w0, aI[0][i]);
                aI[1][i] = ffma2(a,  w1, aI[1][i]);
                aI[2][i] = ffma2(a,  w2, aI[2][i]);
                aH[0][i] = ffma2(hh, w3, aH[0][i]);
                aH[1][i] = ffma2(hh, w4, aH[1][i]);
                aH[2][i] = ffma2(hh, w5, aH[2][i]);
            }
        }
        __syncthreads();
    }

    const int j0 = colB + 2 * cg;
    const float bir0 = b_ih[j0],           bir1 = b_ih[j0 + 1];
    const float biz0 = b_ih[HID + j0],     biz1 = b_ih[HID + j0 + 1];
    const float bin0 = b_ih[2 * HID + j0], bin1 = b_ih[2 * HID + j0 + 1];
    const float bhr0 = b_hh[j0],           bhr1 = b_hh[j0 + 1];
    const float bhz0 = b_hh[HID + j0],     bhz1 = b_hh[HID + j0 + 1];
    const float bhn0 = b_hh[2 * HID + j0], bhn1 = b_hh[2 * HID + j0 + 1];

#pragma unroll
    for (int i = 0; i < 4; i++) {
        int node = node0 + rowg * 4 + i;
        if (node < NN) {
            float ir0, ir1, iz0, iz1, in0, in1;
            float hr0, hr1, hz0, hz1, hn0, hn1;
            unpack2(aI[0][i], ir0, ir1);
            unpack2(aI[1][i], iz0, iz1);
            unpack2(aI[2][i], in0, in1);
            unpack2(aH[0][i], hr0, hr1);
            unpack2(aH[1][i], hz0, hz1);
            unpack2(aH[2][i], hn0, hn1);

            float2 hp2 = *(const float2*)(h + (size_t)node * HID + j0);

            float r0 = sigmoidf_(ir0 + bir0 + hr0 + bhr0);
            float z0 = sigmoidf_(iz0 + biz0 + hz0 + bhz0);
            float n0 = tanhf(in0 + bin0 + r0 * (hn0 + bhn0));
            float r1 = sigmoidf_(ir1 + bir1 + hr1 + bhr1);
            float z1 = sigmoidf_(iz1 + biz1 + hz1 + bhz1);
            float n1 = tanhf(in1 + bin1 + r1 * (hn1 + bhn1));

            *(float2*)&hnew[(size_t)node * HID + j0] =
                make_float2((1.f - z0) * n0 + z0 * hp2.x,
                            (1.f - z1) * n1 + z1 * hp2.y);
        }
    }
}

// ---------------- relu -> out proj (128->40) -> log_softmax ----------------
__global__ __launch_bounds__(128) void out_kernel(
    const float* __restrict__ h, const float* __restrict__ W_out,
    const float* __restrict__ b_out, float* __restrict__ out)
{
    __shared__ float sW[128][48];
    __shared__ float sB[48];
    __shared__ float sH[4][128];

    const int tid = threadIdx.x;
    for (int i = tid; i < 128 * 48; i += 128) {
        int k = i / 48, cc = i % 48;
        sW[k][cc] = (cc < OUTC) ? W_out[(size_t)k * OUTC + cc] : 0.f;
    }
    if (tid < 48) sB[tid] = (tid < OUTC) ? b_out[tid] : 0.f;

    const int w = tid >> 5, lane = tid & 31;
    const int node = blockIdx.x * 4 + w;
    float4 hv = *(const float4*)(h + (size_t)node * HID + lane * 4);
    hv.x = fmaxf(hv.x, 0.f); hv.y = fmaxf(hv.y, 0.f);
    hv.z = fmaxf(hv.z, 0.f); hv.w = fmaxf(hv.w, 0.f);
    *(float4*)&sH[w][lane * 4] = hv;
    __syncthreads();

    const int c1 = 32 + (lane & 7);
    float acc0 = 0.f, acc1 = 0.f;
#pragma unroll 4
    for (int k = 0; k < 128; k++) {
        float a = sH[w][k];
        acc0 += a * sW[k][lane];
        acc1 += a * sW[k][c1];
    }
    float v0 = acc0 + sB[lane];
    float v1 = acc1 + sB[c1];
    const bool has1 = lane < 8;

    float mx = fmaxf(v0, has1 ? v1 : -INFINITY);
#pragma unroll
    for (int o = 16; o > 0; o >>= 1) mx = fmaxf(mx, __shfl_xor_sync(0xFFFFFFFFu, mx, o));
    float s = expf(v0 - mx) + (has1 ? expf(v1 - mx) : 0.f);
#pragma unroll
    for (int o = 16; o > 0; o >>= 1) s += __shfl_xor_sync(0xFFFFFFFFu, s, o);
    float lse = mx + logf(s);

    out[(size_t)node * OUTC + lane] = v0 - lse;
    if (has1) out[(size_t)node * OUTC + 32 + lane] = v1 - lse;
}

// ---------------- launch ----------------
extern "C" void kernel_launch(void* const* d_in, const int* in_sizes, int n_in,
                              void* d_out, int out_size)
{
    const float* x       = (const float*)d_in[0];
    const int*   ei      = (const int*)  d_in[1];
    const float* W_in    = (const float*)d_in[2];
    const float* b_in    = (const float*)d_in[3];
    const float* layer_W = (const float*)d_in[4];
    const float* W_ih    = (const float*)d_in[5];
    const float* W_hh    = (const float*)d_in[6];
    const float* b_ih    = (const float*)d_in[7];
    const float* b_hh    = (const float*)d_in[8];
    const float* W_out   = (const float*)d_in[9];
    const float* b_out   = (const float*)d_in[10];

    float *hbuf, *mbuf, *aggbuf, *hnewbuf;
    cudaGetSymbolAddress((void**)&hbuf,    g_h);
    cudaGetSymbolAddress((void**)&mbuf,    g_m);
    cudaGetSymbolAddress((void**)&aggbuf,  g_agg);
    cudaGetSymbolAddress((void**)&hnewbuf, g_hnew);

    const int gemmBlocks = (NN + 127) / 128;   // 391
    const int gruBlocksX = (NN + 63) / 64;     // 782
    const int n4 = NN * HID / 4;               // 1.6M

    gemm128_f2_kernel<<<gemmBlocks, 256>>>(x, W_in, b_in, hbuf);

    float* hcur = hbuf;
    float* hnext = hnewbuf;
    for (int L = 0; L < 3; L++) {
        gemm128_f2_kernel<<<gemmBlocks, 256>>>(hcur, layer_W + (size_t)L * HID * HID, nullptr, mbuf);
        zero_kernel<<<(n4 + 255) / 256, 256>>>((float4*)aggbuf, n4);
        scatter_kernel<<<NE / 8, 256>>>(ei, mbuf, aggbuf);
        gru_f2_kernel<<<dim3(gruBlocksX, 4), 256>>>(aggbuf, hcur, W_ih, W_hh, b_ih, b_hh, hnext);
        float* t = hcur; hcur = hnext; hnext = t;
    }

    out_kernel<<<NN / 4, 128>>>(hcur, W_out, b_out, (float*)d_out);
}

// round 6
// speedup vs baseline: 1.5190x; 1.4624x over previous
#include <cuda_runtime.h>
#include <cuda_bf16.h>
#include <math.h>
#include <stdint.h>

#define NN 50000
#define NE 800000
#define HID 128
#define OUTC 40

// ---------------- scratch (no allocation allowed) ----------------
__device__ float g_h[(size_t)NN * HID];
__device__ float g_hnew[(size_t)NN * HID];
__device__ float g_m[(size_t)NN * HID];
__device__ float g_agg[(size_t)NN * HID];

// ---------------- helpers ----------------
__device__ __forceinline__ uint32_t f2tf(float f)
{
    uint32_t r;
    asm("cvt.rna.tf32.f32 %0, %1;" : "=r"(r) : "f"(f));
    return r;
}

__device__ __forceinline__ void mma_tf32(float c[4],
    uint32_t a0, uint32_t a1, uint32_t a2, uint32_t a3,
    uint32_t b0, uint32_t b1)
{
    asm("mma.sync.aligned.m16n8k8.row.col.f32.tf32.tf32.f32 "
        "{%0,%1,%2,%3}, {%4,%5,%6,%7}, {%8,%9}, {%0,%1,%2,%3};"
        : "+f"(c[0]), "+f"(c[1]), "+f"(c[2]), "+f"(c[3])
        : "r"(a0), "r"(a1), "r"(a2), "r"(a3), "r"(b0), "r"(b1));
}

__device__ __forceinline__ float sigmoidf_(float x) { return 1.f / (1.f + expf(-x)); }

// k-permuted smem layout within each 8-wide k-block: phys(k) = 2*(k%4) + k/4.
// => (k=tx, k=tx+4) are adjacent -> one LDS.64 per fragment pair.
// Store an f4 covering k = 4a..4a+3 (a = k4&1) at phys base (k4>>1)*8 + a, stride 2.

// ---------------- C[M,128] = A[M,128] @ W[128,128] (+bias), tf32 MMA ----------------
// Block 256 = 8 warps: 4 M-warps x 2 N-warps. Block tile m64 x n128, warp m16 x n64.
__global__ __launch_bounds__(256, 2) void gemm_tf32_kernel(
    const float* __restrict__ A, const float* __restrict__ W,
    const float* __restrict__ bias, float* __restrict__ C)
{
    __shared__ uint32_t sA[64][36];    // [row][k-perm], pad 36
    __shared__ uint32_t sB[128][36];   // [n][k-perm]

    const int tid  = threadIdx.x;
    const int lane = tid & 31;
    const int warp = tid >> 5;
    const int wm   = warp & 3;         // 0..3 (M)
    const int wn   = warp >> 2;        // 0..1 (N)
    const int ty   = lane >> 2;        // 0..7
    const int tx   = lane & 3;         // 0..3
    const int row0 = blockIdx.x * 64;

    float c[8][4];
#pragma unroll
    for (int t = 0; t < 8; t++)
#pragma unroll
        for (int i = 0; i < 4; i++) c[t][i] = 0.f;

    for (int kc = 0; kc < 128; kc += 32) {
        // A tile: 64 rows x 32 k = 512 f4, 2 per thread
#pragma unroll
        for (int r = 0; r < 2; r++) {
            int id  = tid + r * 256;       // 0..511
            int row = id >> 3;             // 0..63
            int k4  = id & 7;              // 0..7
            int rr  = row0 + row; if (rr >= NN) rr = NN - 1;
            float4 v = *(const float4*)(A + (size_t)rr * HID + kc + k4 * 4);
            int base = (k4 >> 1) * 8 + (k4 & 1);
            sA[row][base + 0] = f2tf(v.x);
            sA[row][base + 2] = f2tf(v.y);
            sA[row][base + 4] = f2tf(v.z);
            sA[row][base + 6] = f2tf(v.w);
        }
        // B tile: W[k][n] -> sB[n][k-perm]; 32 k x 128 n = 1024 f4, 4 per thread
#pragma unroll
        for (int r = 0; r < 4; r++) {
            int id = tid + r * 256;        // 0..1023
            int kk = id & 31;              // 0..31
            int nq = id >> 5;              // 0..31
            float4 v = *(const float4*)(W + (size_t)(kc + kk) * HID + nq * 4);
            int base = ((kk & 7) >> 1) * 8 + (kk & 1) + (kk >> 3) * 0; // within-8 perm
            int k8   = (kk >> 3) * 8;
            int phys = k8 + 2 * ((kk & 7) & 3) + ((kk & 7) >> 2);
            (void)base;
            sB[nq * 4 + 0][phys] = f2tf(v.x);
            sB[nq * 4 + 1][phys] = f2tf(v.y);
            sB[nq * 4 + 2][phys] = f2tf(v.z);
            sB[nq * 4 + 3][phys] = f2tf(v.w);
        }
        __syncthreads();

#pragma unroll
        for (int k8 = 0; k8 < 32; k8 += 8) {
            uint2 a02 = *(const uint2*)&sA[wm * 16 + ty][k8 + 2 * tx];
            uint2 a13 = *(const uint2*)&sA[wm * 16 + ty + 8][k8 + 2 * tx];
#pragma unroll
            for (int t = 0; t < 8; t++) {
                int n = wn * 64 + t * 8 + ty;
                uint2 b = *(const uint2*)&sB[n][k8 + 2 * tx];
                mma_tf32(c[t], a02.x, a13.x, a02.y, a13.y, b.x, b.y);
            }
        }
        __syncthreads();
    }

    const int r0 = row0 + wm * 16 + ty;
    const int r1 = r0 + 8;
#pragma unroll
    for (int t = 0; t < 8; t++) {
        int col = wn * 64 + t * 8 + 2 * tx;
        float b0 = bias ? bias[col]     : 0.f;
        float b1 = bias ? bias[col + 1] : 0.f;
        if (r0 < NN)
            *(float2*)&C[(size_t)r0 * HID + col] = make_float2(c[t][0] + b0, c[t][1] + b1);
        if (r1 < NN)
            *(float2*)&C[(size_t)r1 * HID + col] = make_float2(c[t][2] + b0, c[t][3] + b1);
    }
}

// ---------------- zero agg ----------------
__global__ void zero_kernel(float4* __restrict__ p, int n4)
{
    int i = blockIdx.x * blockDim.x + threadIdx.x;
    if (i < n4) p[i] = make_float4(0.f, 0.f, 0.f, 0.f);
}

// ---------------- scatter-add over edges (warp per edge, v4 RED) ----------------
__global__ __launch_bounds__(256) void scatter_kernel(
    const int* __restrict__ ei, const float* __restrict__ m, float* __restrict__ agg)
{
    const int e = blockIdx.x * 8 + (threadIdx.x >> 5);
    const int lane = threadIdx.x & 31;
    const int src = __ldg(ei + e);
    const int dst = __ldg(ei + NE + e);
    float4 v = *(const float4*)(m + (size_t)src * HID + lane * 4);
    float* p = agg + (size_t)dst * HID + lane * 4;
    asm volatile("red.global.add.v4.f32 [%0], {%1,%2,%3,%4};"
                 :: "l"(p), "f"(v.x), "f"(v.y), "f"(v.z), "f"(v.w) : "memory");
}

// ---------------- fused GRU with tf32 MMA ----------------
// grid (ceil(NN/64), 4). Block 256 = 8 warps: 4 M x 2 N. Tile m64 x n32, warp m16 x n16.
// 6 GEMM outputs per (node,col): gates r,z,n for input (agg@W_ih^T) and hidden (h@W_hh^T).
__global__ __launch_bounds__(256, 2) void gru_tf32_kernel(
    const float* __restrict__ agg, const float* __restrict__ h,
    const float* __restrict__ W_ih, const float* __restrict__ W_hh,
    const float* __restrict__ b_ih, const float* __restrict__ b_hh,
    float* __restrict__ hnew)
{
    __shared__ uint32_t sAg[64][36];
    __shared__ uint32_t sH[64][36];
    __shared__ uint32_t sW[6][32][36];   // [gate][n][k-perm]

    const int tid   = threadIdx.x;
    const int lane  = tid & 31;
    const int warp  = tid >> 5;
    const int wm    = warp & 3;
    const int wn    = warp >> 2;
    const int ty    = lane >> 2;
    const int tx    = lane & 3;
    const int node0 = blockIdx.x * 64;
    const int colB  = blockIdx.y * 32;

    float c[6][2][4];
#pragma unroll
    for (int g = 0; g < 6; g++)
#pragma unroll
        for (int t = 0; t < 2; t++)
#pragma unroll
            for (int i = 0; i < 4; i++) c[g][t][i] = 0.f;

    for (int kc = 0; kc < 128; kc += 32) {
        // agg/h tiles: 64 rows x 32 k = 512 f4 each, 2 per thread per array
#pragma unroll
        for (int r = 0; r < 2; r++) {
            int id  = tid + r * 256;
            int row = id >> 3;             // 0..63
            int k4  = id & 7;
            int rr  = node0 + row; if (rr >= NN) rr = NN - 1;
            float4 va = *(const float4*)(agg + (size_t)rr * HID + kc + k4 * 4);
            float4 vh = *(const float4*)(h   + (size_t)rr * HID + kc + k4 * 4);
            int base = (k4 >> 1) * 8 + (k4 & 1);
            sAg[row][base + 0] = f2tf(va.x);
            sAg[row][base + 2] = f2tf(va.y);
            sAg[row][base + 4] = f2tf(va.z);
            sAg[row][base + 6] = f2tf(va.w);
            sH[row][base + 0] = f2tf(vh.x);
            sH[row][base + 2] = f2tf(vh.y);
            sH[row][base + 4] = f2tf(vh.z);
            sH[row][base + 6] = f2tf(vh.w);
        }
        // weights: 6 gates x 32 n-rows x 8 f4 = 1536 f4, 6 per thread
#pragma unroll
        for (int r = 0; r < 6; r++) {
            int id    = tid + r * 256;     // 0..1535
            int nrow  = id >> 3;           // 0..191
            int g     = nrow >> 5;         // 0..5
            int n     = nrow & 31;
            int k4    = id & 7;
            const float* Wp = (g < 3) ? W_ih : W_hh;
            int grow = (g % 3) * HID + colB + n;
            float4 v = *(const float4*)(Wp + (size_t)grow * HID + kc + k4 * 4);
            int base = (k4 >> 1) * 8 + (k4 & 1);
            sW[g][n][base + 0] = f2tf(v.x);
            sW[g][n][base + 2] = f2tf(v.y);
            sW[g][n][base + 4] = f2tf(v.z);
            sW[g][n][base + 6] = f2tf(v.w);
        }
        __syncthreads();

#pragma unroll
        for (int k8 = 0; k8 < 32; k8 += 8) {
            uint2 ag02 = *(const uint2*)&sAg[wm * 16 + ty][k8 + 2 * tx];
            uint2 ag13 = *(const uint2*)&sAg[wm * 16 + ty + 8][k8 + 2 * tx];
            uint2 h02  = *(const uint2*)&sH[wm * 16 + ty][k8 + 2 * tx];
            uint2 h13  = *(const uint2*)&sH[wm * 16 + ty + 8][k8 + 2 * tx];
#pragma unroll
            for (int t = 0; t < 2; t++) {
                int n = wn * 16 + t * 8 + ty;
#pragma unroll
                for (int g = 0; g < 3; g++) {
                    uint2 b = *(const uint2*)&sW[g][n][k8 + 2 * tx];
                    mma_tf32(c[g][t], ag02.x, ag13.x, ag02.y, ag13.y, b.x, b.y);
                }
#pragma unroll
                for (int g = 3; g < 6; g++) {
                    uint2 b = *(const uint2*)&sW[g][n][k8 + 2 * tx];
                    mma_tf32(c[g][t], h02.x, h13.x, h02.y, h13.y, b.x, b.y);
                }
            }
        }
        __syncthreads();
    }

    // epilogue: gates + h_new
    const int r0 = node0 + wm * 16 + ty;
    const int r1 = r0 + 8;
#pragma unroll
    for (int t = 0; t < 2; t++) {
        int j = colB + wn * 16 + t * 8 + 2 * tx;
        float bir0 = b_ih[j],           bir1 = b_ih[j + 1];
        float biz0 = b_ih[HID + j],     biz1 = b_ih[HID + j + 1];
        float bin0 = b_ih[2 * HID + j], bin1 = b_ih[2 * HID + j + 1];
        float bhr0 = b_hh[j],           bhr1 = b_hh[j + 1];
        float bhz0 = b_hh[HID + j],     bhz1 = b_hh[HID + j + 1];
        float bhn0 = b_hh[2 * HID + j], bhn1 = b_hh[2 * HID + j + 1];

        if (r0 < NN) {
            float2 hp = *(const float2*)(h + (size_t)r0 * HID + j);
            float rr0 = sigmoidf_(c[0][t][0] + bir0 + c[3][t][0] + bhr0);
            float zz0 = sigmoidf_(c[1][t][0] + biz0 + c[4][t][0] + bhz0);
            float nn0 = tanhf(c[2][t][0] + bin0 + rr0 * (c[5][t][0] + bhn0));
            float rr1 = sigmoidf_(c[0][t][1] + bir1 + c[3][t][1] + bhr1);
            float zz1 = sigmoidf_(c[1][t][1] + biz1 + c[4][t][1] + bhz1);
            float nn1 = tanhf(c[2][t][1] + bin1 + rr1 * (c[5][t][1] + bhn1));
            *(float2*)&hnew[(size_t)r0 * HID + j] =
                make_float2((1.f - zz0) * nn0 + zz0 * hp.x,
                            (1.f - zz1) * nn1 + zz1 * hp.y);
        }
        if (r1 < NN) {
            float2 hp = *(const float2*)(h + (size_t)r1 * HID + j);
            float rr0 = sigmoidf_(c[0][t][2] + bir0 + c[3][t][2] + bhr0);
            float zz0 = sigmoidf_(c[1][t][2] + biz0 + c[4][t][2] + bhz0);
            float nn0 = tanhf(c[2][t][2] + bin0 + rr0 * (c[5][t][2] + bhn0));
            float rr1 = sigmoidf_(c[0][t][3] + bir1 + c[3][t][3] + bhr1);
            float zz1 = sigmoidf_(c[1][t][3] + biz1 + c[4][t][3] + bhz1);
            float nn1 = tanhf(c[2][t][3] + bin1 + rr1 * (c[5][t][3] + bhn1));
            *(float2*)&hnew[(size_t)r1 * HID + j] =
                make_float2((1.f - zz0) * nn0 + zz0 * hp.x,
                            (1.f - zz1) * nn1 + zz1 * hp.y);
        }
    }
}

// ---------------- relu -> out proj (128->40) -> log_softmax ----------------
__global__ __launch_bounds__(128) void out_kernel(
    const float* __restrict__ h, const float* __restrict__ W_out,
    const float* __restrict__ b_out, float* __restrict__ out)
{
    __shared__ float sW[128][48];
    __shared__ float sB[48];
    __shared__ float sH[4][128];

    const int tid = threadIdx.x;
    for (int i = tid; i < 128 * 48; i += 128) {
        int k = i / 48, cc = i % 48;
        sW[k][cc] = (cc < OUTC) ? W_out[(size_t)k * OUTC + cc] : 0.f;
    }
    if (tid < 48) sB[tid] = (tid < OUTC) ? b_out[tid] : 0.f;

    const int w = tid >> 5, lane = tid & 31;
    const int node = blockIdx.x * 4 + w;
    float4 hv = *(const float4*)(h + (size_t)node * HID + lane * 4);
    hv.x = fmaxf(hv.x, 0.f); hv.y = fmaxf(hv.y, 0.f);
    hv.z = fmaxf(hv.z, 0.f); hv.w = fmaxf(hv.w, 0.f);
    *(float4*)&sH[w][lane * 4] = hv;
    __syncthreads();

    const int c1 = 32 + (lane & 7);
    float acc0 = 0.f, acc1 = 0.f;
#pragma unroll 4
    for (int k = 0; k < 128; k++) {
        float a = sH[w][k];
        acc0 += a * sW[k][lane];
        acc1 += a * sW[k][c1];
    }
    float v0 = acc0 + sB[lane];
    float v1 = acc1 + sB[c1];
    const bool has1 = lane < 8;

    float mx = fmaxf(v0, has1 ? v1 : -INFINITY);
#pragma unroll
    for (int o = 16; o > 0; o >>= 1) mx = fmaxf(mx, __shfl_xor_sync(0xFFFFFFFFu, mx, o));
    float s = expf(v0 - mx) + (has1 ? expf(v1 - mx) : 0.f);
#pragma unroll
    for (int o = 16; o > 0; o >>= 1) s += __shfl_xor_sync(0xFFFFFFFFu, s, o);
    float lse = mx + logf(s);

    out[(size_t)node * OUTC + lane] = v0 - lse;
    if (has1) out[(size_t)node * OUTC + 32 + lane] = v1 - lse;
}

// ---------------- launch ----------------
extern "C" void kernel_launch(void* const* d_in, const int* in_sizes, int n_in,
                              void* d_out, int out_size)
{
    const float* x       = (const float*)d_in[0];
    const int*   ei      = (const int*)  d_in[1];
    const float* W_in    = (const float*)d_in[2];
    const float* b_in    = (const float*)d_in[3];
    const float* layer_W = (const float*)d_in[4];
    const float* W_ih    = (const float*)d_in[5];
    const float* W_hh    = (const float*)d_in[6];
    const float* b_ih    = (const float*)d_in[7];
    const float* b_hh    = (const float*)d_in[8];
    const float* W_out   = (const float*)d_in[9];
    const float* b_out   = (const float*)d_in[10];

    float *hbuf, *mbuf, *aggbuf, *hnewbuf;
    cudaGetSymbolAddress((void**)&hbuf,    g_h);
    cudaGetSymbolAddress((void**)&mbuf,    g_m);
    cudaGetSymbolAddress((void**)&aggbuf,  g_agg);
    cudaGetSymbolAddress((void**)&hnewbuf, g_hnew);

    const int mmBlocks = (NN + 63) / 64;   // 782
    const int n4 = NN * HID / 4;           // 1.6M

    gemm_tf32_kernel<<<mmBlocks, 256>>>(x, W_in, b_in, hbuf);

    float* hcur = hbuf;
    float* hnext = hnewbuf;
    for (int L = 0; L < 3; L++) {
        gemm_tf32_kernel<<<mmBlocks, 256>>>(hcur, layer_W + (size_t)L * HID * HID, nullptr, mbuf);
        zero_kernel<<<(n4 + 255) / 256, 256>>>((float4*)aggbuf, n4);
        scatter_kernel<<<NE / 8, 256>>>(ei, mbuf, aggbuf);
        gru_tf32_kernel<<<dim3(mmBlocks, 4), 256>>>(aggbuf, hcur, W_ih, W_hh, b_ih, b_hh, hnext);
        float* t = hcur; hcur = hnext; hnext = t;
    }

    out_kernel<<<NN / 4, 128>>>(hcur, W_out, b_out, (float*)d_out);
}

// round 12
// speedup vs baseline: 1.7019x; 1.1205x over previous
#include <cuda_runtime.h>
#include <cuda_bf16.h>
#include <math.h>
#include <stdint.h>

#define NN 50000
#define NE 800000
#define HID 128
#define OUTC 40

// ---------------- scratch (no allocation allowed; 256B-aligned for vector access) ----------------
__device__ __align__(256) float g_h[(size_t)NN * HID];
__device__ __align__(256) float g_hnew[(size_t)NN * HID];
__device__ __align__(256) float g_agg[(size_t)NN * HID];
__device__ __align__(256) float g_Wc[3 * 3 * HID * HID];   // per-layer combined W @ W_ih^T, [384][128] each

// ---------------- helpers ----------------
__device__ __forceinline__ uint32_t f2tf(float f)
{
    uint32_t r;
    asm("cvt.rna.tf32.f32 %0, %1;" : "=r"(r) : "f"(f));
    return r;
}

__device__ __forceinline__ void mma_tf32(float c[4],
    uint32_t a0, uint32_t a1, uint32_t a2, uint32_t a3,
    uint32_t b0, uint32_t b1)
{
    asm("mma.sync.aligned.m16n8k8.row.col.f32.tf32.tf32.f32 "
        "{%0,%1,%2,%3}, {%4,%5,%6,%7}, {%8,%9}, {%0,%1,%2,%3};"
        : "+f"(c[0]), "+f"(c[1]), "+f"(c[2]), "+f"(c[3])
        : "r"(a0), "r"(a1), "r"(a2), "r"(a3), "r"(b0), "r"(b1));
}

__device__ __forceinline__ float sigmoidf_(float x) { return 1.f / (1.f + expf(-x)); }

// ---------------- combine: Wc_L[j][k'] = sum_c layer_W[L][k'][c] * W_ih[j][c] ----------------
// grid (12, 4, 3), block 256. Tile: 32 j-rows x 32 k'-rows, full c=128 in smem.
// Prep kernel (~10us total): SCALAR loads/stores only — zero alignment risk.
__global__ __launch_bounds__(256) void combine_kernel(
    const float* __restrict__ layer_W, const float* __restrict__ W_ih,
    float* __restrict__ Wc)
{
    __shared__ float sWih[32][132];
    __shared__ float sW[32][132];

    const int L   = blockIdx.z;
    const int j0  = blockIdx.x * 32;   // 0..383
    const int kp0 = blockIdx.y * 32;   // 0..127
    const float* Wl = layer_W + (size_t)L * HID * HID;

    for (int i = threadIdx.x; i < 32 * 128; i += 256) {
        int row = i >> 7;            // 0..31
        int cc  = i & 127;           // 0..127
        sWih[row][cc] = W_ih[(size_t)(j0 + row) * HID + cc];
        sW[row][cc]   = Wl[(size_t)(kp0 + row) * HID + cc];
    }
    __syncthreads();

    const int j  = threadIdx.x & 31;
    const int kp = (threadIdx.x >> 5) * 4;
    float acc[4] = {0.f, 0.f, 0.f, 0.f};
#pragma unroll 4
    for (int c = 0; c < 128; c++) {
        float wij = sWih[j][c];
        acc[0] += wij * sW[kp + 0][c];
        acc[1] += wij * sW[kp + 1][c];
        acc[2] += wij * sW[kp + 2][c];
        acc[3] += wij * sW[kp + 3][c];
    }
    float* outp = Wc + (size_t)L * 3 * HID * HID + (size_t)(j0 + j) * HID + kp0 + kp;
    outp[0] = acc[0]; outp[1] = acc[1]; outp[2] = acc[2]; outp[3] = acc[3];
}

// ---------------- C[M,128] = A[M,128] @ W[128,128] (+bias), tf32 MMA ----------------
__global__ __launch_bounds__(256, 2) void gemm_tf32_kernel(
    const float* __restrict__ A, const float* __restrict__ W,
    const float* __restrict__ bias, float* __restrict__ C)
{
    __shared__ uint32_t sA[64][36];
    __shared__ uint32_t sB[128][36];

    const int tid  = threadIdx.x;
    const int lane = tid & 31;
    const int warp = tid >> 5;
    const int wm   = warp & 3;
    const int wn   = warp >> 2;
    const int ty   = lane >> 2;
    const int tx   = lane & 3;
    const int row0 = blockIdx.x * 64;

    float c[8][4];
#pragma unroll
    for (int t = 0; t < 8; t++)
#pragma unroll
        for (int i = 0; i < 4; i++) c[t][i] = 0.f;

    for (int kc = 0; kc < 128; kc += 32) {
#pragma unroll
        for (int r = 0; r < 2; r++) {
            int id  = tid + r * 256;
            int row = id >> 3;
            int k4  = id & 7;
            int rr  = row0 + row; if (rr >= NN) rr = NN - 1;
            float4 v = *(const float4*)(A + (size_t)rr * HID + kc + k4 * 4);
            int base = (k4 >> 1) * 8 + (k4 & 1);
            sA[row][base + 0] = f2tf(v.x);
            sA[row][base + 2] = f2tf(v.y);
            sA[row][base + 4] = f2tf(v.z);
            sA[row][base + 6] = f2tf(v.w);
        }
#pragma unroll
        for (int r = 0; r < 4; r++) {
            int id = tid + r * 256;
            int kk = id & 31;
            int nq = id >> 5;
            float4 v = *(const float4*)(W + (size_t)(kc + kk) * HID + nq * 4);
            int k8   = (kk >> 3) * 8;
            int phys = k8 + 2 * ((kk & 7) & 3) + ((kk & 7) >> 2);
            sB[nq * 4 + 0][phys] = f2tf(v.x);
            sB[nq * 4 + 1][phys] = f2tf(v.y);
            sB[nq * 4 + 2][phys] = f2tf(v.z);
            sB[nq * 4 + 3][phys] = f2tf(v.w);
        }
        __syncthreads();

#pragma unroll
        for (int k8 = 0; k8 < 32; k8 += 8) {
            uint2 a02 = *(const uint2*)&sA[wm * 16 + ty][k8 + 2 * tx];
            uint2 a13 = *(const uint2*)&sA[wm * 16 + ty + 8][k8 + 2 * tx];
#pragma unroll
            for (int t = 0; t < 8; t++) {
                int n = wn * 64 + t * 8 + ty;
                uint2 b = *(const uint2*)&sB[n][k8 + 2 * tx];
                mma_tf32(c[t], a02.x, a13.x, a02.y, a13.y, b.x, b.y);
            }
        }
        __syncthreads();
    }

    const int r0 = row0 + wm * 16 + ty;
    const int r1 = r0 + 8;
#pragma unroll
    for (int t = 0; t < 8; t++) {
        int col = wn * 64 + t * 8 + 2 * tx;
        float b0 = bias ? bias[col]     : 0.f;
        float b1 = bias ? bias[col + 1] : 0.f;
        if (r0 < NN)
            *(float2*)&C[(size_t)r0 * HID + col] = make_float2(c[t][0] + b0, c[t][1] + b1);
        if (r1 < NN)
            *(float2*)&C[(size_t)r1 * HID + col] = make_float2(c[t][2] + b0, c[t][3] + b1);
    }
}

// ---------------- zero agg ----------------
__global__ void zero_kernel(float4* __restrict__ p, int n4)
{
    int i = blockIdx.x * blockDim.x + threadIdx.x;
    if (i < n4) p[i] = make_float4(0.f, 0.f, 0.f, 0.f);
}

// ---------------- scatter-add h over edges (warp per edge, v4 RED) ----------------
__global__ __launch_bounds__(256) void scatter_kernel(
    const int* __restrict__ ei, const float* __restrict__ h, float* __restrict__ agg)
{
    const int e = blockIdx.x * 8 + (threadIdx.x >> 5);
    const int lane = threadIdx.x & 31;
    const int src = __ldg(ei + e);
    const int dst = __ldg(ei + NE + e);
    float4 v = *(const float4*)(h + (size_t)src * HID + lane * 4);
    float* p = agg + (size_t)dst * HID + lane * 4;
    asm volatile("red.global.add.v4.f32 [%0], {%1,%2,%3,%4};"
                 :: "l"(p), "f"(v.x), "f"(v.y), "f"(v.z), "f"(v.w) : "memory");
}

// ---------------- fused GRU with tf32 MMA ----------------
// gi = aggH @ Wc^T (combined), gh = h @ W_hh^T. grid (ceil(NN/64), 4).
__global__ __launch_bounds__(256, 2) void gru_tf32_kernel(
    const float* __restrict__ agg, const float* __restrict__ h,
    const float* __restrict__ Wc, const float* __restrict__ W_hh,
    const float* __restrict__ b_ih, const float* __restrict__ b_hh,
    float* __restrict__ hnew)
{
    __shared__ uint32_t sAg[64][36];
    __shared__ uint32_t sH[64][36];
    __shared__ uint32_t sW[6][32][36];

    const int tid   = threadIdx.x;
    const int lane  = tid & 31;
    const int warp  = tid >> 5;
    const int wm    = warp & 3;
    const int wn    = warp >> 2;
    const int ty    = lane >> 2;
    const int tx    = lane & 3;
    const int node0 = blockIdx.x * 64;
    const int colB  = blockIdx.y * 32;

    float c[6][2][4];
#pragma unroll
    for (int g = 0; g < 6; g++)
#pragma unroll
        for (int t = 0; t < 2; t++)
#pragma unroll
            for (int i = 0; i < 4; i++) c[g][t][i] = 0.f;

    for (int kc = 0; kc < 128; kc += 32) {
#pragma unroll
        for (int r = 0; r < 2; r++) {
            int id  = tid + r * 256;
            int row = id >> 3;
            int k4  = id & 7;
            int rr  = node0 + row; if (rr >= NN) rr = NN - 1;
            float4 va = *(const float4*)(agg + (size_t)rr * HID + kc + k4 * 4);
            float4 vh = *(const float4*)(h   + (size_t)rr * HID + kc + k4 * 4);
            int base = (k4 >> 1) * 8 + (k4 & 1);
            sAg[row][base + 0] = f2tf(va.x);
            sAg[row][base + 2] = f2tf(va.y);
            sAg[row][base + 4] = f2tf(va.z);
            sAg[row][base + 6] = f2tf(va.w);
            sH[row][base + 0] = f2tf(vh.x);
            sH[row][base + 2] = f2tf(vh.y);
            sH[row][base + 4] = f2tf(vh.z);
            sH[row][base + 6] = f2tf(vh.w);
        }
#pragma unroll
        for (int r = 0; r < 6; r++) {
            int id    = tid + r * 256;
            int nrow  = id >> 3;           // 0..191
            int g     = nrow >> 5;         // 0..5
            int n     = nrow & 31;
            int k4    = id & 7;
            const float* Wp = (g < 3) ? Wc : W_hh;
            int grow = (g % 3) * HID + colB + n;
            float4 v = *(const float4*)(Wp + (size_t)grow * HID + kc + k4 * 4);
            int base = (k4 >> 1) * 8 + (k4 & 1);
            sW[g][n][base + 0] = f2tf(v.x);
            sW[g][n][base + 2] = f2tf(v.y);
            sW[g][n][base + 4] = f2tf(v.z);
            sW[g][n][base + 6] = f2tf(v.w);
        }
        __syncthreads();

#pragma unroll
        for (int k8 = 0; k8 < 32; k8 += 8) {
            uint2 ag02 = *(const uint2*)&sAg[wm * 16 + ty][k8 + 2 * tx];
            uint2 ag13 = *(const uint2*)&sAg[wm * 16 + ty + 8][k8 + 2 * tx];
            uint2 h02  = *(const uint2*)&sH[wm * 16 + ty][k8 + 2 * tx];
            uint2 h13  = *(const uint2*)&sH[wm * 16 + ty + 8][k8 + 2 * tx];
#pragma unroll
            for (int t = 0; t < 2; t++) {
                int n = wn * 16 + t * 8 + ty;
#pragma unroll
                for (int g = 0; g < 3; g++) {
                    uint2 b = *(const uint2*)&sW[g][n][k8 + 2 * tx];
                    mma_tf32(c[g][t], ag02.x, ag13.x, ag02.y, ag13.y, b.x, b.y);
                }
#pragma unroll
                for (int g = 3; g < 6; g++) {
                    uint2 b = *(const uint2*)&sW[g][n][k8 + 2 * tx];
                    mma_tf32(c[g][t], h02.x, h13.x, h02.y, h13.y, b.x, b.y);
                }
            }
        }
        __syncthreads();
    }

    const int r0 = node0 + wm * 16 + ty;
    const int r1 = r0 + 8;
#pragma unroll
    for (int t = 0; t < 2; t++) {
        int j = colB + wn * 16 + t * 8 + 2 * tx;
        float bir0 = b_ih[j],           bir1 = b_ih[j + 1];
        float biz0 = b_ih[HID + j],     biz1 = b_ih[HID + j + 1];
        float bin0 = b_ih[2 * HID + j], bin1 = b_ih[2 * HID + j + 1];
        float bhr0 = b_hh[j],           bhr1 = b_hh[j + 1];
        float bhz0 = b_hh[HID + j],     bhz1 = b_hh[HID + j + 1];
        float bhn0 = b_hh[2 * HID + j], bhn1 = b_hh[2 * HID + j + 1];

        if (r0 < NN) {
            float2 hp = *(const float2*)(h + (size_t)r0 * HID + j);
            float rr0 = sigmoidf_(c[0][t][0] + bir0 + c[3][t][0] + bhr0);
            float zz0 = sigmoidf_(c[1][t][0] + biz0 + c[4][t][0] + bhz0);
            float nn0 = tanhf(c[2][t][0] + bin0 + rr0 * (c[5][t][0] + bhn0));
            float rr1 = sigmoidf_(c[0][t][1] + bir1 + c[3][t][1] + bhr1);
            float zz1 = sigmoidf_(c[1][t][1] + biz1 + c[4][t][1] + bhz1);
            float nn1 = tanhf(c[2][t][1] + bin1 + rr1 * (c[5][t][1] + bhn1));
            *(float2*)&hnew[(size_t)r0 * HID + j] =
                make_float2((1.f - zz0) * nn0 + zz0 * hp.x,
                            (1.f - zz1) * nn1 + zz1 * hp.y);
        }
        if (r1 < NN) {
            float2 hp = *(const float2*)(h + (size_t)r1 * HID + j);
            float rr0 = sigmoidf_(c[0][t][2] + bir0 + c[3][t][2] + bhr0);
            float zz0 = sigmoidf_(c[1][t][2] + biz0 + c[4][t][2] + bhz0);
            float nn0 = tanhf(c[2][t][2] + bin0 + rr0 * (c[5][t][2] + bhn0));
            float rr1 = sigmoidf_(c[0][t][3] + bir1 + c[3][t][3] + bhr1);
            float zz1 = sigmoidf_(c[1][t][3] + biz1 + c[4][t][3] + bhz1);
            float nn1 = tanhf(c[2][t][3] + bin1 + rr1 * (c[5][t][3] + bhn1));
            *(float2*)&hnew[(size_t)r1 * HID + j] =
                make_float2((1.f - zz0) * nn0 + zz0 * hp.x,
                            (1.f - zz1) * nn1 + zz1 * hp.y);
        }
    }
}

// ---------------- relu -> out proj (128->40) -> log_softmax ----------------
__global__ __launch_bounds__(128) void out_kernel(
    const float* __restrict__ h, const float* __restrict__ W_out,
    const float* __restrict__ b_out, float* __restrict__ out)
{
    __shared__ float sW[128][48];
    __shared__ float sB[48];
    __shared__ float sH[4][128];

    const int tid = threadIdx.x;
    for (int i = tid; i < 128 * 48; i += 128) {
        int k = i / 48, cc = i % 48;
        sW[k][cc] = (cc < OUTC) ? W_out[(size_t)k * OUTC + cc] : 0.f;
    }
    if (tid < 48) sB[tid] = (tid < OUTC) ? b_out[tid] : 0.f;

    const int w = tid >> 5, lane = tid & 31;
    const int node = blockIdx.x * 4 + w;
    float4 hv = *(const float4*)(h + (size_t)node * HID + lane * 4);
    hv.x = fmaxf(hv.x, 0.f); hv.y = fmaxf(hv.y, 0.f);
    hv.z = fmaxf(hv.z, 0.f); hv.w = fmaxf(hv.w, 0.f);
    *(float4*)&sH[w][lane * 4] = hv;
    __syncthreads();

    const int c1 = 32 + (lane & 7);
    float acc0 = 0.f, acc1 = 0.f;
#pragma unroll 4
    for (int k = 0; k < 128; k++) {
        float a = sH[w][k];
        acc0 += a * sW[k][lane];
        acc1 += a * sW[k][c1];
    }
    float v0 = acc0 + sB[lane];
    float v1 = acc1 + sB[c1];
    const bool has1 = lane < 8;

    float mx = fmaxf(v0, has1 ? v1 : -INFINITY);
#pragma unroll
    for (int o = 16; o > 0; o >>= 1) mx = fmaxf(mx, __shfl_xor_sync(0xFFFFFFFFu, mx, o));
    float s = expf(v0 - mx) + (has1 ? expf(v1 - mx) : 0.f);
#pragma unroll
    for (int o = 16; o > 0; o >>= 1) s += __shfl_xor_sync(0xFFFFFFFFu, s, o);
    float lse = mx + logf(s);

    out[(size_t)node * OUTC + lane] = v0 - lse;
    if (has1) out[(size_t)node * OUTC + 32 + lane] = v1 - lse;
}

// ---------------- launch ----------------
extern "C" void kernel_launch(void* const* d_in, const int* in_sizes, int n_in,
                              void* d_out, int out_size)
{
    const float* x       = (const float*)d_in[0];
    const int*   ei      = (const int*)  d_in[1];
    const float* W_in    = (const float*)d_in[2];
    const float* b_in    = (const float*)d_in[3];
    const float* layer_W = (const float*)d_in[4];
    const float* W_ih    = (const float*)d_in[5];
    const float* W_hh    = (const float*)d_in[6];
    const float* b_ih    = (const float*)d_in[7];
    const float* b_hh    = (const float*)d_in[8];
    const float* W_out   = (const float*)d_in[9];
    const float* b_out   = (const float*)d_in[10];

    float *hbuf, *aggbuf, *hnewbuf, *wcbuf;
    cudaGetSymbolAddress((void**)&hbuf,    g_h);
    cudaGetSymbolAddress((void**)&aggbuf,  g_agg);
    cudaGetSymbolAddress((void**)&hnewbuf, g_hnew);
    cudaGetSymbolAddress((void**)&wcbuf,   g_Wc);

    const int mmBlocks = (NN + 63) / 64;   // 782
    const int n4 = NN * HID / 4;           // 1.6M

    // precompute combined message+input-gate weights for all 3 layers
    combine_kernel<<<dim3(12, 4, 3), 256>>>(layer_W, W_ih, wcbuf);

    gemm_tf32_kernel<<<mmBlocks, 256>>>(x, W_in, b_in, hbuf);

    float* hcur = hbuf;
    float* hnext = hnewbuf;
    for (int L = 0; L < 3; L++) {
        zero_kernel<<<(n4 + 255) / 256, 256>>>((float4*)aggbuf, n4);
        scatter_kernel<<<NE / 8, 256>>>(ei, hcur, aggbuf);
        gru_tf32_kernel<<<dim3(mmBlocks, 4), 256>>>(
            aggbuf, hcur, wcbuf + (size_t)L * 3 * HID * HID, W_hh, b_ih, b_hh, hnext);
        float* t = hcur; hcur = hnext; hnext = t;
    }

    out_kernel<<<NN / 4, 128>>>(hcur, W_out, b_out, (float*)d_out);
}